// round 12
// baseline (speedup 1.0000x reference)
#include <cuda_runtime.h>
#include <cuda_fp16.h>

#define NX    512
#define NPTS  32768
#define CCH   64
#define NB    4
#define PLANE (NX * NX)
#define BVOL  (PLANE * CCH)

// NHWC fp16 scratch (b, py, px, c). 134 MB.
__device__ __half g_xt[(size_t)NB * BVOL];

// ---------------------------------------------------------------------------
// Kernel 1: NCHW fp32 -> NHWC fp16. Tile = 64 px x 64 ch, 256 threads.
// Loads: 4x LDG.128 per thread. Pack: 2x STG.128 per thread.
// ---------------------------------------------------------------------------
__global__ __launch_bounds__(256) void transpose_kernel(const float* __restrict__ x)
{
    __shared__ float s[64][65];               // [channel][pixel]

    const int tile = blockIdx.x;
    const int b    = tile >> 12;              // 4096 tiles per batch
    const int p0   = (tile & 4095) * 64;

    const int slot = threadIdx.x & 15;        // float4 slot (4 px)
    const int c0   = threadIdx.x >> 4;        // 0..15

    const float* xb = x + (size_t)b * BVOL;
    #pragma unroll
    for (int c = c0; c < 64; c += 16) {
        const float4 v = __ldcs((const float4*)(xb + (size_t)c * PLANE + p0 + slot * 4));
        s[c][slot * 4 + 0] = v.x;
        s[c][slot * 4 + 1] = v.y;
        s[c][slot * 4 + 2] = v.z;
        s[c][slot * 4 + 3] = v.w;
    }
    __syncthreads();

    __half* yb = g_xt + (size_t)b * BVOL + (size_t)p0 * CCH;
    #pragma unroll
    for (int i = threadIdx.x; i < 64 * 8; i += 256) {
        const int p   = i >> 3;               // pixel
        const int oct = i & 7;                // 8-channel octet
        __half2 h[4];
        #pragma unroll
        for (int j = 0; j < 4; j++)
            h[j] = __floats2half2_rn(s[oct * 8 + 2 * j][p], s[oct * 8 + 2 * j + 1][p]);
        *(int4*)(yb + (size_t)p * CCH + oct * 8) = *(const int4*)h;   // STG.128
    }
}

// ---------------------------------------------------------------------------
// Kernel 2: gather. Block = 256 threads, 32 consecutive points.
// Phase 2 (round-10 optimum): lane = channel quad (4 ch via LDG.64),
// half-warp per point, 2 iterations x 2 points per warp.
// Phase 3: float2 stores along n (STG.64).
// ---------------------------------------------------------------------------
__global__ __launch_bounds__(256) void gather_kernel(
    const float* __restrict__ coords,
    float*       __restrict__ out)
{
    __shared__ __align__(16) float s_w[32][12];    // 9 used, 48B rows
    __shared__ __align__(16) int   s_off[32][12];  // half-elem offsets in batch
    __shared__ __align__(8)  float s_out[64][34];  // [channel][point], 8B-aligned rows

    const int p0g = blockIdx.x * 32;
    const int b   = p0g / NPTS;
    const int n0  = p0g % NPTS;
    const int tid = threadIdx.x;

    // ---- Phase 1: per-point normalized 3x3 weights + offsets ----
    if (tid < 32) {
        const int   n    = n0 + tid;
        const float cy   = coords[((size_t)b * NPTS + n) * 2 + 0];
        const float cx   = coords[((size_t)b * NPTS + n) * 2 + 1];
        const float posx = cx * 511.0f;
        const float posy = cy * 511.0f;
        const float rx   = rintf(posx);       // jnp.round = half-to-even
        const float ry   = rintf(posy);

        float wx[3] = {0.f, 0.f, 0.f};
        float wy[3] = {0.f, 0.f, 0.f};
        #pragma unroll
        for (int j = 0; j < 9; j++) {
            const float o  = 1.5f - 0.375f * (float)j;           // off_n[j]
            const float px = fminf(fmaxf(rx - o, 0.f), 512.f);   // clip hi = nx (ref quirk)
            const float py = fminf(fmaxf(ry - o, 0.f), 512.f);
            const float dx = px - posx;
            const float dy = py - posy;
            wx[j / 3] += __expf(-2.f * dx * dx);  // normal const cancels in norm
            wy[j / 3] += __expf(-2.f * dy * dy);
        }

        float w9[9];
        float s = 0.f;
        #pragma unroll
        for (int a = 0; a < 3; a++)
            #pragma unroll
            for (int c2 = 0; c2 < 3; c2++) {
                const float w = wx[a] * wy[c2];
                w9[a * 3 + c2] = w;
                s += w;
            }
        const float inv = 1.0f / s;

        const int irx = (int)rx;
        const int iry = (int)ry;
        int ixs[3], iys[3];
        #pragma unroll
        for (int a = 0; a < 3; a++) {
            ixs[a] = min(max(irx + 1 - a, 0), NX - 1);
            iys[a] = min(max(iry + 1 - a, 0), NX - 1);
        }

        #pragma unroll
        for (int a = 0; a < 3; a++)
            #pragma unroll
            for (int c2 = 0; c2 < 3; c2++) {
                s_w[tid][a * 3 + c2]   = w9[a * 3 + c2] * inv;
                s_off[tid][a * 3 + c2] = (ixs[a] * NX + iys[c2]) * CCH;
            }
    }
    __syncthreads();

    // ---- Phase 2: dense fp16 NHWC gather, LDG.64 per tap ----
    const int lane = tid & 31;
    const int warp = tid >> 5;
    const int cq   = lane & 15;               // channel quad (4 ch)
    const int sub  = lane >> 4;               // half-warp -> point select
    const __half* bp = g_xt + (size_t)b * BVOL + 4 * cq;

    #pragma unroll
    for (int it = 0; it < 2; it++) {
        const int p = warp * 4 + it * 2 + sub;

        const int4 oA = *(const int4*)&s_off[p][0];
        const int4 oB = *(const int4*)&s_off[p][4];
        const int  o8 = s_off[p][8];
        const int off[9] = {oA.x, oA.y, oA.z, oA.w, oB.x, oB.y, oB.z, oB.w, o8};

        const float4 wA = *(const float4*)&s_w[p][0];
        const float4 wB = *(const float4*)&s_w[p][4];
        const float  w8 = s_w[p][8];
        const float w[9] = {wA.x, wA.y, wA.z, wA.w, wB.x, wB.y, wB.z, wB.w, w8};

        int2 v[9];
        #pragma unroll
        for (int k = 0; k < 9; k++)
            v[k] = *(const int2*)(bp + off[k]);      // LDG.64, 4 channels

        float ax = 0.f, ay = 0.f, az = 0.f, aw = 0.f;
        #pragma unroll
        for (int k = 0; k < 9; k++) {
            const float2 f0 = __half22float2(*(const __half2*)&v[k].x);
            const float2 f1 = __half22float2(*(const __half2*)&v[k].y);
            ax += w[k] * f0.x;  ay += w[k] * f0.y;
            az += w[k] * f1.x;  aw += w[k] * f1.y;
        }
        s_out[4 * cq + 0][p] = ax;
        s_out[4 * cq + 1][p] = ay;
        s_out[4 * cq + 2][p] = az;
        s_out[4 * cq + 3][p] = aw;
    }
    __syncthreads();

    // ---- Phase 3: coalesced (c, n) writes, float2 along n (STG.64) ----
    float* ob = out + (size_t)b * CCH * NPTS + n0;
    #pragma unroll
    for (int i = tid; i < CCH * 16; i += 256) {
        const int j2 = i & 15;                // point pair
        const int c  = i >> 4;                // channel
        const float2 v = *(const float2*)&s_out[c][2 * j2];
        __stcs((float2*)(ob + (size_t)c * NPTS + 2 * j2), v);
    }
}

extern "C" void kernel_launch(void* const* d_in, const int* in_sizes, int n_in,
                              void* d_out, int out_size) {
    const float* x      = (const float*)d_in[0];
    const float* coords = (const float*)d_in[1];
    if (n_in >= 2 && in_sizes[0] == NB * NPTS * 2) {   // defensive swap
        const float* t = x; x = coords; coords = t;
    }
    float* out = (float*)d_out;

    transpose_kernel<<<NB * (PLANE / 64), 256>>>(x);
    gather_kernel<<<(NB * NPTS) / 32, 256>>>(coords, out);
}

// round 13
// speedup vs baseline: 1.0287x; 1.0287x over previous
#include <cuda_runtime.h>
#include <cuda_fp16.h>

#define NX    512
#define NPTS  32768
#define CCH   64
#define NB    4
#define PLANE (NX * NX)
#define BVOL  (PLANE * CCH)

// NHWC fp16 scratch (b, py, px, c). 134 MB.
__device__ __half g_xt[(size_t)NB * BVOL];

// ---------------------------------------------------------------------------
// Kernel 1: NCHW fp32 -> NHWC fp16. Tile = 64 px x 64 ch, 256 threads.
// Loads: 4x LDG.128 per thread. Pack: 2x STG.128 per thread.
// ---------------------------------------------------------------------------
__global__ __launch_bounds__(256) void transpose_kernel(const float* __restrict__ x)
{
    __shared__ float s[64][65];               // [channel][pixel]

    const int tile = blockIdx.x;
    const int b    = tile >> 12;              // 4096 tiles per batch
    const int p0   = (tile & 4095) * 64;

    const int slot = threadIdx.x & 15;        // float4 slot (4 px)
    const int c0   = threadIdx.x >> 4;        // 0..15

    const float* xb = x + (size_t)b * BVOL;
    #pragma unroll
    for (int c = c0; c < 64; c += 16) {
        const float4 v = __ldcs((const float4*)(xb + (size_t)c * PLANE + p0 + slot * 4));
        s[c][slot * 4 + 0] = v.x;
        s[c][slot * 4 + 1] = v.y;
        s[c][slot * 4 + 2] = v.z;
        s[c][slot * 4 + 3] = v.w;
    }
    __syncthreads();

    __half* yb = g_xt + (size_t)b * BVOL + (size_t)p0 * CCH;
    #pragma unroll
    for (int i = threadIdx.x; i < 64 * 8; i += 256) {
        const int p   = i >> 3;               // pixel
        const int oct = i & 7;                // 8-channel octet
        __half2 h[4];
        #pragma unroll
        for (int j = 0; j < 4; j++)
            h[j] = __floats2half2_rn(s[oct * 8 + 2 * j][p], s[oct * 8 + 2 * j + 1][p]);
        *(int4*)(yb + (size_t)p * CCH + oct * 8) = *(const int4*)h;   // STG.128
    }
}

// ---------------------------------------------------------------------------
// Kernel 2: gather. Block = 256 threads, 32 consecutive points.
// Phase 1: lanes 0-3 of EACH warp compute its own 4 points' weights
//          (8x parallel MUFU, __syncwarp instead of block barrier).
// Phase 2 (round-10 optimum): lane = channel quad, LDG.64 per tap,
//          half-warp per point, 2 iterations x 2 points per warp.
// Phase 3: stride-33 smem (round-10 bank profile) + STG.64 global stores.
// ---------------------------------------------------------------------------
__global__ __launch_bounds__(256) void gather_kernel(
    const float* __restrict__ coords,
    float*       __restrict__ out)
{
    __shared__ __align__(16) float s_w[32][12];    // 9 used, 48B rows
    __shared__ __align__(16) int   s_off[32][12];  // half-elem offsets in batch
    __shared__ float s_out[64][33];                // [channel][point]

    const int p0g = blockIdx.x * 32;
    const int b   = p0g / NPTS;
    const int n0  = p0g % NPTS;
    const int tid = threadIdx.x;
    const int lane = tid & 31;
    const int warp = tid >> 5;

    // ---- Phase 1: per-warp weight computation for its own 4 points ----
    if (lane < 4) {
        const int   pt   = warp * 4 + lane;       // point index in block
        const int   n    = n0 + pt;
        const float cy   = coords[((size_t)b * NPTS + n) * 2 + 0];
        const float cx   = coords[((size_t)b * NPTS + n) * 2 + 1];
        const float posx = cx * 511.0f;
        const float posy = cy * 511.0f;
        const float rx   = rintf(posx);       // jnp.round = half-to-even
        const float ry   = rintf(posy);

        float wx[3] = {0.f, 0.f, 0.f};
        float wy[3] = {0.f, 0.f, 0.f};
        #pragma unroll
        for (int j = 0; j < 9; j++) {
            const float o  = 1.5f - 0.375f * (float)j;           // off_n[j]
            const float px = fminf(fmaxf(rx - o, 0.f), 512.f);   // clip hi = nx (ref quirk)
            const float py = fminf(fmaxf(ry - o, 0.f), 512.f);
            const float dx = px - posx;
            const float dy = py - posy;
            wx[j / 3] += __expf(-2.f * dx * dx);  // normal const cancels in norm
            wy[j / 3] += __expf(-2.f * dy * dy);
        }

        float w9[9];
        float s = 0.f;
        #pragma unroll
        for (int a = 0; a < 3; a++)
            #pragma unroll
            for (int c2 = 0; c2 < 3; c2++) {
                const float w = wx[a] * wy[c2];
                w9[a * 3 + c2] = w;
                s += w;
            }
        const float inv = 1.0f / s;

        const int irx = (int)rx;
        const int iry = (int)ry;
        int ixs[3], iys[3];
        #pragma unroll
        for (int a = 0; a < 3; a++) {
            ixs[a] = min(max(irx + 1 - a, 0), NX - 1);
            iys[a] = min(max(iry + 1 - a, 0), NX - 1);
        }

        #pragma unroll
        for (int a = 0; a < 3; a++)
            #pragma unroll
            for (int c2 = 0; c2 < 3; c2++) {
                s_w[pt][a * 3 + c2]   = w9[a * 3 + c2] * inv;
                s_off[pt][a * 3 + c2] = (ixs[a] * NX + iys[c2]) * CCH;
            }
    }
    __syncwarp();                              // warp-local dependency only

    // ---- Phase 2: dense fp16 NHWC gather, LDG.64 per tap ----
    const int cq  = lane & 15;                // channel quad (4 ch)
    const int sub = lane >> 4;                // half-warp -> point select
    const __half* bp = g_xt + (size_t)b * BVOL + 4 * cq;

    #pragma unroll
    for (int it = 0; it < 2; it++) {
        const int p = warp * 4 + it * 2 + sub;

        const int4 oA = *(const int4*)&s_off[p][0];
        const int4 oB = *(const int4*)&s_off[p][4];
        const int  o8 = s_off[p][8];
        const int off[9] = {oA.x, oA.y, oA.z, oA.w, oB.x, oB.y, oB.z, oB.w, o8};

        const float4 wA = *(const float4*)&s_w[p][0];
        const float4 wB = *(const float4*)&s_w[p][4];
        const float  w8 = s_w[p][8];
        const float w[9] = {wA.x, wA.y, wA.z, wA.w, wB.x, wB.y, wB.z, wB.w, w8};

        int2 v[9];
        #pragma unroll
        for (int k = 0; k < 9; k++)
            v[k] = *(const int2*)(bp + off[k]);      // LDG.64, 4 channels

        float ax = 0.f, ay = 0.f, az = 0.f, aw = 0.f;
        #pragma unroll
        for (int k = 0; k < 9; k++) {
            const float2 f0 = __half22float2(*(const __half2*)&v[k].x);
            const float2 f1 = __half22float2(*(const __half2*)&v[k].y);
            ax += w[k] * f0.x;  ay += w[k] * f0.y;
            az += w[k] * f1.x;  aw += w[k] * f1.y;
        }
        s_out[4 * cq + 0][p] = ax;
        s_out[4 * cq + 1][p] = ay;
        s_out[4 * cq + 2][p] = az;
        s_out[4 * cq + 3][p] = aw;
    }
    __syncthreads();

    // ---- Phase 3: coalesced (c, n) writes, STG.64 from two LDS.32 ----
    float* ob = out + (size_t)b * CCH * NPTS + n0;
    #pragma unroll
    for (int i = tid; i < CCH * 16; i += 256) {
        const int j2 = i & 15;                // point pair
        const int c  = i >> 4;                // channel
        const float2 v = make_float2(s_out[c][2 * j2], s_out[c][2 * j2 + 1]);
        __stcs((float2*)(ob + (size_t)c * NPTS + 2 * j2), v);
    }
}

extern "C" void kernel_launch(void* const* d_in, const int* in_sizes, int n_in,
                              void* d_out, int out_size) {
    const float* x      = (const float*)d_in[0];
    const float* coords = (const float*)d_in[1];
    if (n_in >= 2 && in_sizes[0] == NB * NPTS * 2) {   // defensive swap
        const float* t = x; x = coords; coords = t;
    }
    float* out = (float*)d_out;

    transpose_kernel<<<NB * (PLANE / 64), 256>>>(x);
    gather_kernel<<<(NB * NPTS) / 32, 256>>>(coords, out);
}